// round 16
// baseline (speedup 1.0000x reference)
#include <cuda_runtime.h>
#include <cuda_fp16.h>
#include <cstdint>

#define NN 50000
#define EE 800000
#define NWTOT 393216
#define BM 128
#define P32 20   /* words per SMEM row: 40 halves, 80 B pitch */

// ---------------- static device scratch (no runtime alloc allowed) ----------
__device__ __half g_xHi[(size_t)NN * 128], g_xLo[(size_t)NN * 128];
__device__ __half g_hHiA[(size_t)NN * 512], g_hLoA[(size_t)NN * 512];
__device__ __half g_hHiB[(size_t)NN * 512], g_hLoB[(size_t)NN * 512];
__device__ __half g_aggHi[(size_t)NN * 256], g_aggLo[(size_t)NN * 256];
__device__ int   g_deg[NN];
__device__ float g_deg_inv[NN];
__device__ int   g_row_off[NN];
__device__ int   g_fill[NN];
__device__ int   g_csr_src[EE];
__device__ int   g_counter;
__device__ __half g_Whi[NWTOT];
__device__ __half g_Wlo[NWTOT];

// ---------------- fp16 split helpers ----------------------------------------
__device__ __forceinline__ void split2p(float x, float y, uint32_t& hi2, uint32_t& lo2) {
    asm("cvt.rn.f16x2.f32 %0, %1, %2;" : "=r"(hi2) : "f"(y), "f"(x));
    float hx, hy;
    asm("{\n\t.reg .b16 l, h;\n\tmov.b32 {l, h}, %2;\n\t"
        "cvt.f32.f16 %0, l;\n\tcvt.f32.f16 %1, h;\n\t}"
        : "=f"(hx), "=f"(hy) : "r"(hi2));
    float lx = x - hx, ly = y - hy;
    asm("cvt.rn.f16x2.f32 %0, %1, %2;" : "=r"(lo2) : "f"(ly), "f"(lx));
}

// accumulate 8 fp16 (uint4) into 8 fp32
__device__ __forceinline__ void acc8(float* a, uint4 v) {
    float2 f0 = __half22float2(*reinterpret_cast<__half2*>(&v.x));
    float2 f1 = __half22float2(*reinterpret_cast<__half2*>(&v.y));
    float2 f2 = __half22float2(*reinterpret_cast<__half2*>(&v.z));
    float2 f3 = __half22float2(*reinterpret_cast<__half2*>(&v.w));
    a[0] += f0.x; a[1] += f0.y; a[2] += f1.x; a[3] += f1.y;
    a[4] += f2.x; a[5] += f2.y; a[6] += f3.x; a[7] += f3.y;
}

// ---------------- graph build ----------------------------------------------
__global__ void k_zero_deg() {
    int i = blockIdx.x * blockDim.x + threadIdx.x;
    if (i < NN) g_deg[i] = 0;
    if (i == 0) g_counter = 0;
}

__global__ void k_count_deg(const int* __restrict__ dst) {
    int e = blockIdx.x * blockDim.x + threadIdx.x;
    if (e < EE) atomicAdd(&g_deg[dst[e]], 1);
}

__global__ void k_offsets() {
    __shared__ int sh[256];
    __shared__ int base;
    int t = threadIdx.x;
    int i = blockIdx.x * 256 + t;
    int d = (i < NN) ? g_deg[i] : 0;
    sh[t] = d;
    __syncthreads();
    #pragma unroll
    for (int off = 1; off < 256; off <<= 1) {
        int v = (t >= off) ? sh[t - off] : 0;
        __syncthreads();
        sh[t] += v;
        __syncthreads();
    }
    int incl = sh[t];
    if (t == 255) base = atomicAdd(&g_counter, incl);
    __syncthreads();
    if (i < NN) {
        int o = base + incl - d;
        g_row_off[i] = o;
        g_fill[i]    = o;
        g_deg_inv[i] = 1.0f / fmaxf((float)d, 1.0f);
    }
}

__global__ void k_fill_csr(const int* __restrict__ src, const int* __restrict__ dst) {
    int e = blockIdx.x * blockDim.x + threadIdx.x;
    if (e < EE) {
        int p = atomicAdd(&g_fill[dst[e]], 1);
        g_csr_src[p] = src[e];
    }
}

// ---------------- weight + input pre-conversion -------------------------------
struct WP { const float* w[10]; };

__global__ void k_convW(WP p) {
    const int off[11] = {0, 16384, 32768, 40960, 49152, 57344,
                         65536, 98304, 131072, 262144, 393216};
    int i = blockIdx.x * 256 + threadIdx.x;
    if (i >= NWTOT) return;
    int s = 0;
    #pragma unroll
    for (int j = 1; j < 10; j++) if (i >= off[j]) s = j;
    float v = p.w[s][i - off[s]];
    __half h = __float2half_rn(v);
    g_Whi[i] = h;
    g_Wlo[i] = __float2half_rn(v - __half2float(h));
}

__global__ void k_convX(const float2* __restrict__ x2) {
    int i = blockIdx.x * 256 + threadIdx.x;       // NN*128/2 pairs
    if (i >= NN * 64) return;
    float2 v = x2[i];
    uint32_t h2, l2;
    split2p(v.x, v.y, h2, l2);
    reinterpret_cast<uint32_t*>(g_xHi)[i] = h2;
    reinterpret_cast<uint32_t*>(g_xLo)[i] = l2;
}

// ---------------- aggregation: planar hi/lo, one uint4 gather per lane ------
// blockDim.x = 2*din8 (hi-lanes then lo-lanes), blockDim.y = npb (128 thr total)
__global__ void k_agg_hl(const uint4* __restrict__ hHi, const uint4* __restrict__ hLo,
                         uint4* __restrict__ aggHi, uint4* __restrict__ aggLo,
                         int din8) {
    __shared__ float sh[512];           // (npb*din8) groups x 8 floats = 512 max
    int tx = threadIdx.x, ty = threadIdx.y;
    int n = blockIdx.x * blockDim.y + ty;    // NN divides evenly for all layers
    int isLo = (tx >= din8);
    int kk = tx - (isLo ? din8 : 0);
    const uint4* base = isLo ? hLo : hHi;
    int s = g_row_off[n];
    int e1 = s + g_deg[n];
    float a[8] = {0.f, 0.f, 0.f, 0.f, 0.f, 0.f, 0.f, 0.f};
    int e = s;
    for (; e + 3 < e1; e += 4) {
        int s0 = g_csr_src[e + 0];
        int s1 = g_csr_src[e + 1];
        int s2 = g_csr_src[e + 2];
        int s3 = g_csr_src[e + 3];
        uint4 v0 = base[(size_t)s0 * din8 + kk];
        uint4 v1 = base[(size_t)s1 * din8 + kk];
        uint4 v2 = base[(size_t)s2 * din8 + kk];
        uint4 v3 = base[(size_t)s3 * din8 + kk];
        acc8(a, v0); acc8(a, v1); acc8(a, v2); acc8(a, v3);
    }
    for (; e < e1; e++)
        acc8(a, base[(size_t)g_csr_src[e] * din8 + kk]);

    float* slot = &sh[(ty * din8 + kk) * 8];
    if (isLo) {
        #pragma unroll
        for (int j = 0; j < 8; j++) slot[j] = a[j];
    }
    __syncthreads();
    if (!isLo) {
        float di = g_deg_inv[n];
        uint4 oh, ol;
        float v0, v1;
        v0 = (a[0] + slot[0]) * di; v1 = (a[1] + slot[1]) * di; split2p(v0, v1, oh.x, ol.x);
        v0 = (a[2] + slot[2]) * di; v1 = (a[3] + slot[3]) * di; split2p(v0, v1, oh.y, ol.y);
        v0 = (a[4] + slot[4]) * di; v1 = (a[5] + slot[5]) * di; split2p(v0, v1, oh.z, ol.z);
        v0 = (a[6] + slot[6]) * di; v1 = (a[7] + slot[7]) * di; split2p(v0, v1, oh.w, ol.w);
        aggHi[(size_t)n * din8 + kk] = oh;
        aggLo[(size_t)n * din8 + kk] = ol;
    }
}

// ---------------- fp16 (3x hi/lo split) mma.sync SAGE gemm -------------------
__device__ __forceinline__ void mma_f16(float* c, const uint32_t* a, const uint32_t* b) {
    asm volatile(
        "mma.sync.aligned.m16n8k16.row.col.f32.f16.f16.f32 "
        "{%0,%1,%2,%3}, {%4,%5,%6,%7}, {%8,%9}, {%0,%1,%2,%3};"
        : "+f"(c[0]), "+f"(c[1]), "+f"(c[2]), "+f"(c[3])
        : "r"(a[0]), "r"(a[1]), "r"(a[2]), "r"(a[3]), "r"(b[0]), "r"(b[1]));
}

__device__ __forceinline__ void ldm_x4(uint32_t* r, uint32_t addr) {
    asm volatile("ldmatrix.sync.aligned.m8n8.x4.shared.b16 {%0,%1,%2,%3}, [%4];"
                 : "=r"(r[0]), "=r"(r[1]), "=r"(r[2]), "=r"(r[3]) : "r"(addr));
}
__device__ __forceinline__ void ldm_x2(uint32_t* r, uint32_t addr) {
    asm volatile("ldmatrix.sync.aligned.m8n8.x2.shared.b16 {%0,%1}, [%2];"
                 : "=r"(r[0]), "=r"(r[1]) : "r"(addr));
}

template<int BN>
__global__ __launch_bounds__(256)
void k_gemm_f16(const __half* __restrict__ A0h, const __half* __restrict__ A0l,
                const __half* __restrict__ A1h, const __half* __restrict__ A1l,
                const __half* __restrict__ WhiL, const __half* __restrict__ WloL,
                const __half* __restrict__ WhiR, const __half* __restrict__ WloR,
                const float* __restrict__ bias,
                __half* __restrict__ Chi, __half* __restrict__ Clo,
                int din, int dout)
{
    constexpr int WN = BN / 4;
    constexpr int NT = WN / 8;
    constexpr int A_IT = 2;                   // uint4 (8-half) loads / plane
    constexpr int B_IT = BN / 64;             // 2 or 1

    __shared__ uint32_t AsH[BM * P32], AsL[BM * P32];
    __shared__ uint32_t BsH[BN * P32], BsL[BN * P32];

    int tid = threadIdx.x;
    int wid = tid >> 5, lane = tid & 31;
    int wm = wid >> 2, wn = wid & 3;
    int lr = lane >> 2, q = lane & 3;
    int rowBase = blockIdx.x * BM;
    int colBase = blockIdx.y * BN;

    int aRow = (lane & 7) + 8 * ((lane >> 3) & 1);
    int aCol = 16 * ((lane >> 4) & 1);
    int bRow = lane & 7;
    int bCol = 16 * ((lane >> 3) & 1);
    uint32_t aBaseH = (uint32_t)__cvta_generic_to_shared(AsH) + (wm * 64 + aRow) * 80 + aCol;
    uint32_t aBaseL = (uint32_t)__cvta_generic_to_shared(AsL) + (wm * 64 + aRow) * 80 + aCol;
    uint32_t bBaseH = (uint32_t)__cvta_generic_to_shared(BsH) + (wn * WN + bRow) * 80 + bCol;
    uint32_t bBaseL = (uint32_t)__cvta_generic_to_shared(BsL) + (wn * WN + bRow) * 80 + bCol;

    float acc[4][NT][4];
    #pragma unroll
    for (int i = 0; i < 4; i++)
        #pragma unroll
        for (int j = 0; j < NT; j++)
            #pragma unroll
            for (int p = 0; p < 4; p++) acc[i][j][p] = 0.0f;

    const int K = 2 * din;
    const int nCh = K >> 5;

    uint4 pah[A_IT], pal[A_IT], pbh[B_IT], pbl[B_IT];

    auto loadChunk = [&](int ch) {
        int k0 = ch << 5;
        const __half *Ah, *Al, *Bh, *Bl;
        int kk;
        if (k0 < din) { Ah = A0h; Al = A0l; Bh = WhiL; Bl = WloL; kk = k0; }
        else          { Ah = A1h; Al = A1l; Bh = WhiR; Bl = WloR; kk = k0 - din; }
        #pragma unroll
        for (int it = 0; it < A_IT; it++) {
            int i = tid + it * 256;
            int r = i >> 2, c8 = (i & 3) << 3;
            int gr = rowBase + r;
            if (gr < NN) {
                size_t goff = (size_t)gr * din + kk + c8;
                pah[it] = *reinterpret_cast<const uint4*>(&Ah[goff]);
                pal[it] = *reinterpret_cast<const uint4*>(&Al[goff]);
            } else {
                pah[it] = make_uint4(0, 0, 0, 0);
                pal[it] = make_uint4(0, 0, 0, 0);
            }
        }
        #pragma unroll
        for (int it = 0; it < B_IT; it++) {
            int i = tid + it * 256;
            int r = i >> 2, c8 = (i & 3) << 3;
            size_t goff = (size_t)(colBase + r) * din + kk + c8;
            pbh[it] = *reinterpret_cast<const uint4*>(&Bh[goff]);
            pbl[it] = *reinterpret_cast<const uint4*>(&Bl[goff]);
        }
    };

    loadChunk(0);

    for (int ch = 0; ch < nCh; ch++) {
        // stage A + B: pure uint4 copies
        #pragma unroll
        for (int it = 0; it < A_IT; it++) {
            int i = tid + it * 256;
            int r = i >> 2, w4 = (i & 3) << 2;
            *reinterpret_cast<uint4*>(&AsH[r * P32 + w4]) = pah[it];
            *reinterpret_cast<uint4*>(&AsL[r * P32 + w4]) = pal[it];
        }
        #pragma unroll
        for (int it = 0; it < B_IT; it++) {
            int i = tid + it * 256;
            int r = i >> 2, w4 = (i & 3) << 2;
            *reinterpret_cast<uint4*>(&BsH[r * P32 + w4]) = pbh[it];
            *reinterpret_cast<uint4*>(&BsL[r * P32 + w4]) = pbl[it];
        }
        __syncthreads();

        if (ch + 1 < nCh) loadChunk(ch + 1);   // GMEM latency overlaps MMA

        #pragma unroll
        for (int ks = 0; ks < 2; ks++) {
            uint32_t kb = (uint32_t)(ks * 32);
            uint32_t ah[4][4], al[4][4], bh[NT][2], bl[NT][2];
            #pragma unroll
            for (int mt = 0; mt < 4; mt++) {
                uint32_t moff = (uint32_t)(mt * 16 * 80) + kb;
                ldm_x4(ah[mt], aBaseH + moff);
                ldm_x4(al[mt], aBaseL + moff);
            }
            #pragma unroll
            for (int nt = 0; nt < NT; nt++) {
                uint32_t noff = (uint32_t)(nt * 8 * 80) + kb;
                ldm_x2(bh[nt], bBaseH + noff);
                ldm_x2(bl[nt], bBaseL + noff);
            }
            #pragma unroll
            for (int mt = 0; mt < 4; mt++)
                #pragma unroll
                for (int nt = 0; nt < NT; nt++)
                    mma_f16(acc[mt][nt], ah[mt], bh[nt]);
            #pragma unroll
            for (int mt = 0; mt < 4; mt++)
                #pragma unroll
                for (int nt = 0; nt < NT; nt++)
                    mma_f16(acc[mt][nt], al[mt], bh[nt]);
            #pragma unroll
            for (int mt = 0; mt < 4; mt++)
                #pragma unroll
                for (int nt = 0; nt < NT; nt++)
                    mma_f16(acc[mt][nt], ah[mt], bl[nt]);
        }
        __syncthreads();
    }

    // epilogue: bias + relu + split to hi/lo planes
    #pragma unroll
    for (int mt = 0; mt < 4; mt++) {
        int r0 = rowBase + wm * 64 + mt * 16 + lr;
        int r1 = r0 + 8;
        #pragma unroll
        for (int nt = 0; nt < NT; nt++) {
            int c = colBase + wn * WN + nt * 8 + q * 2;
            float b0 = bias[c], b1 = bias[c + 1];
            if (r0 < NN) {
                float v0 = fmaxf(acc[mt][nt][0] + b0, 0.f);
                float v1 = fmaxf(acc[mt][nt][1] + b1, 0.f);
                uint32_t h2, l2;
                split2p(v0, v1, h2, l2);
                *reinterpret_cast<uint32_t*>(&Chi[(size_t)r0 * dout + c]) = h2;
                *reinterpret_cast<uint32_t*>(&Clo[(size_t)r0 * dout + c]) = l2;
            }
            if (r1 < NN) {
                float v0 = fmaxf(acc[mt][nt][2] + b0, 0.f);
                float v1 = fmaxf(acc[mt][nt][3] + b1, 0.f);
                uint32_t h2, l2;
                split2p(v0, v1, h2, l2);
                *reinterpret_cast<uint32_t*>(&Chi[(size_t)r1 * dout + c]) = h2;
                *reinterpret_cast<uint32_t*>(&Clo[(size_t)r1 * dout + c]) = l2;
            }
        }
    }
}

// ---------------- head: logits = h @ Wout^T + bout; softmax -----------------
__device__ __forceinline__ float4 rec4u(uint2 uh, uint2 ul) {
    float2 fa = __half22float2(*reinterpret_cast<__half2*>(&uh.x));
    float2 fb = __half22float2(*reinterpret_cast<__half2*>(&uh.y));
    float2 fc = __half22float2(*reinterpret_cast<__half2*>(&ul.x));
    float2 fd = __half22float2(*reinterpret_cast<__half2*>(&ul.y));
    return make_float4(fa.x + fc.x, fa.y + fc.y, fb.x + fd.x, fb.y + fd.y);
}

__global__ void k_head(const uint2* __restrict__ hHi, const uint2* __restrict__ hLo,
                       const float4* __restrict__ Wout4,
                       const float* __restrict__ bout, float* __restrict__ out) {
    int gwarp = (blockIdx.x * blockDim.x + threadIdx.x) >> 5;
    int lane  = threadIdx.x & 31;
    if (gwarp >= NN) return;
    size_t base = (size_t)gwarp * 128;
    float s[4] = {0.f, 0.f, 0.f, 0.f};
    #pragma unroll
    for (int it = 0; it < 4; it++) {
        int i = lane + it * 32;
        float4 hv = rec4u(hHi[base + i], hLo[base + i]);
        #pragma unroll
        for (int c = 0; c < 4; c++) {
            float4 wv = Wout4[c * 128 + i];
            s[c] += hv.x * wv.x + hv.y * wv.y + hv.z * wv.z + hv.w * wv.w;
        }
    }
    #pragma unroll
    for (int off = 16; off > 0; off >>= 1)
        #pragma unroll
        for (int c = 0; c < 4; c++)
            s[c] += __shfl_xor_sync(0xFFFFFFFF, s[c], off);
    if (lane == 0) {
        float l[4];
        float m = -1e30f;
        #pragma unroll
        for (int c = 0; c < 4; c++) { l[c] = s[c] + bout[c]; m = fmaxf(m, l[c]); }
        float den = 0.f;
        #pragma unroll
        for (int c = 0; c < 4; c++) { l[c] = __expf(l[c] - m); den += l[c]; }
        float inv = 1.0f / den;
        #pragma unroll
        for (int c = 0; c < 4; c++) out[(size_t)gwarp * 4 + c] = l[c] * inv;
    }
}

// ---------------- driver -----------------------------------------------------
extern "C" void kernel_launch(void* const* d_in, const int* in_sizes, int n_in,
                              void* d_out, int out_size)
{
    const float* x    = (const float*)d_in[0];
    const float* Wl[5] = {(const float*)d_in[1],  (const float*)d_in[4],
                          (const float*)d_in[7],  (const float*)d_in[10],
                          (const float*)d_in[13]};
    const float* bl[5] = {(const float*)d_in[2],  (const float*)d_in[5],
                          (const float*)d_in[8],  (const float*)d_in[11],
                          (const float*)d_in[14]};
    const float* Wr[5] = {(const float*)d_in[3],  (const float*)d_in[6],
                          (const float*)d_in[9],  (const float*)d_in[12],
                          (const float*)d_in[15]};
    const float* Wout = (const float*)d_in[16];
    const float* bout = (const float*)d_in[17];
    const int*   ei   = (const int*)d_in[18];
    const int* src = ei;
    const int* dst = ei + EE;

    __half *xHi, *xLo, *hHiA, *hLoA, *hHiB, *hLoB, *aggHi, *aggLo, *whi, *wlo;
    cudaGetSymbolAddress((void**)&xHi,  g_xHi);
    cudaGetSymbolAddress((void**)&xLo,  g_xLo);
    cudaGetSymbolAddress((void**)&hHiA, g_hHiA);
    cudaGetSymbolAddress((void**)&hLoA, g_hLoA);
    cudaGetSymbolAddress((void**)&hHiB, g_hHiB);
    cudaGetSymbolAddress((void**)&hLoB, g_hLoB);
    cudaGetSymbolAddress((void**)&aggHi, g_aggHi);
    cudaGetSymbolAddress((void**)&aggLo, g_aggLo);
    cudaGetSymbolAddress((void**)&whi, g_Whi);
    cudaGetSymbolAddress((void**)&wlo, g_Wlo);

    // 0. convert weights + input once per call
    WP wp;
    for (int i = 0; i < 5; i++) { wp.w[2 * i] = Wl[i]; wp.w[2 * i + 1] = Wr[i]; }
    k_convW<<<(NWTOT + 255) / 256, 256>>>(wp);
    k_convX<<<(NN * 64 + 255) / 256, 256>>>((const float2*)x);

    // 1. build CSR by dst
    k_zero_deg<<<(NN + 255) / 256, 256>>>();
    k_count_deg<<<(EE + 255) / 256, 256>>>(dst);
    k_offsets<<<(NN + 255) / 256, 256>>>();
    k_fill_csr<<<(EE + 255) / 256, 256>>>(src, dst);

    // 2. layers
    const int dins[5]  = {128, 128, 64, 128, 256};
    const int douts[5] = {128,  64, 128, 256, 512};
    const int woff[10] = {0, 16384, 32768, 40960, 49152, 57344,
                          65536, 98304, 131072, 262144};
    const __half* hHi = xHi;
    const __half* hLo = xLo;
    __half* hiBufs[2] = {hHiA, hHiB};
    __half* loBufs[2] = {hLoA, hLoB};
    for (int i = 0; i < 5; i++) {
        int din = dins[i], dout = douts[i];
        int din8 = din / 8;
        int lanes = 2 * din8;
        int npb = 128 / lanes;            // NN divides evenly: 4, 4, 8, 4, 2
        dim3 ablk(lanes, npb);
        k_agg_hl<<<NN / npb, ablk>>>((const uint4*)hHi, (const uint4*)hLo,
                                     (uint4*)aggHi, (uint4*)aggLo, din8);
        __half* nHi = hiBufs[i & 1];
        __half* nLo = loBufs[i & 1];
        const __half* whl = whi + woff[2 * i];
        const __half* wll = wlo + woff[2 * i];
        const __half* whr = whi + woff[2 * i + 1];
        const __half* wlr = wlo + woff[2 * i + 1];
        if (dout >= 128) {
            dim3 grid((NN + BM - 1) / BM, dout / 128);
            k_gemm_f16<128><<<grid, 256>>>(aggHi, aggLo, hHi, hLo,
                                           whl, wll, whr, wlr, bl[i],
                                           nHi, nLo, din, dout);
        } else {
            dim3 grid((NN + BM - 1) / BM, 1);
            k_gemm_f16<64><<<grid, 256>>>(aggHi, aggLo, hHi, hLo,
                                          whl, wll, whr, wlr, bl[i],
                                          nHi, nLo, din, dout);
        }
        hHi = nHi; hLo = nLo;
    }

    // 3. head + softmax
    k_head<<<(NN * 32 + 255) / 256, 256>>>((const uint2*)hHi, (const uint2*)hLo,
                                           (const float4*)Wout, bout, (float*)d_out);
}

// round 17
// speedup vs baseline: 1.2033x; 1.2033x over previous
#include <cuda_runtime.h>
#include <cuda_fp16.h>
#include <cstdint>

#define NN 50000
#define EE 800000
#define NWTOT 393216
#define BM 128
#define P32 20   /* words per SMEM row: 40 halves, 80 B pitch */

// ---------------- static device scratch (no runtime alloc allowed) ----------
__device__ float g_bufA[(size_t)NN * 512];
__device__ float g_bufB[(size_t)NN * 512];
__device__ float g_agg [(size_t)NN * 256];
__device__ __half g_x16 [(size_t)NN * 128];
__device__ __half g_h16A[(size_t)NN * 512];
__device__ __half g_h16B[(size_t)NN * 512];
__device__ int   g_deg[NN];
__device__ float g_deg_inv[NN];
__device__ int   g_row_off[NN];
__device__ int   g_fill[NN];
__device__ int   g_csr_src[EE];
__device__ int   g_counter;
__device__ __half g_Whi[NWTOT];
__device__ __half g_Wlo[NWTOT];

// ---------------- graph build ----------------------------------------------
__global__ void k_zero_deg() {
    int i = blockIdx.x * blockDim.x + threadIdx.x;
    if (i < NN) g_deg[i] = 0;
    if (i == 0) g_counter = 0;
}

__global__ void k_count_deg(const int* __restrict__ dst) {
    int e = blockIdx.x * blockDim.x + threadIdx.x;
    if (e < EE) atomicAdd(&g_deg[dst[e]], 1);
}

__global__ void k_offsets() {
    __shared__ int sh[256];
    __shared__ int base;
    int t = threadIdx.x;
    int i = blockIdx.x * 256 + t;
    int d = (i < NN) ? g_deg[i] : 0;
    sh[t] = d;
    __syncthreads();
    #pragma unroll
    for (int off = 1; off < 256; off <<= 1) {
        int v = (t >= off) ? sh[t - off] : 0;
        __syncthreads();
        sh[t] += v;
        __syncthreads();
    }
    int incl = sh[t];
    if (t == 255) base = atomicAdd(&g_counter, incl);
    __syncthreads();
    if (i < NN) {
        int o = base + incl - d;
        g_row_off[i] = o;
        g_fill[i]    = o;
        g_deg_inv[i] = 1.0f / fmaxf((float)d, 1.0f);
    }
}

__global__ void k_fill_csr(const int* __restrict__ src, const int* __restrict__ dst) {
    int e = blockIdx.x * blockDim.x + threadIdx.x;
    if (e < EE) {
        int p = atomicAdd(&g_fill[dst[e]], 1);
        g_csr_src[p] = src[e];
    }
}

// ---------------- weight + input pre-conversion -------------------------------
struct WP { const float* w[10]; };

__global__ void k_convW(WP p) {
    const int off[11] = {0, 16384, 32768, 40960, 49152, 57344,
                         65536, 98304, 131072, 262144, 393216};
    int i = blockIdx.x * 256 + threadIdx.x;
    if (i >= NWTOT) return;
    int s = 0;
    #pragma unroll
    for (int j = 1; j < 10; j++) if (i >= off[j]) s = j;
    float v = p.w[s][i - off[s]];
    __half h = __float2half_rn(v);
    g_Whi[i] = h;
    g_Wlo[i] = __float2half_rn(v - __half2float(h));
}

// fp16 copy of x for aggregation gathers
__global__ void k_convX16(const float2* __restrict__ x2) {
    int i = blockIdx.x * 256 + threadIdx.x;      // NN*128/2 pairs
    if (i >= NN * 64) return;
    float2 v = x2[i];
    uint32_t p;
    asm("cvt.rn.f16x2.f32 %0, %1, %2;" : "=r"(p) : "f"(v.y), "f"(v.x));
    reinterpret_cast<uint32_t*>(g_x16)[i] = p;
}

// ---------------- aggregation: fp16 gather, fp32 accumulate/output ----------
__device__ __forceinline__ void acc8(float* a, uint4 v) {
    float2 f0 = __half22float2(*reinterpret_cast<__half2*>(&v.x));
    float2 f1 = __half22float2(*reinterpret_cast<__half2*>(&v.y));
    float2 f2 = __half22float2(*reinterpret_cast<__half2*>(&v.z));
    float2 f3 = __half22float2(*reinterpret_cast<__half2*>(&v.w));
    a[0] += f0.x; a[1] += f0.y; a[2] += f1.x; a[3] += f1.y;
    a[4] += f2.x; a[5] += f2.y; a[6] += f3.x; a[7] += f3.y;
}

// blockDim = (din8, npb); lane k covers elements [8k, 8k+8)
__global__ void k_aggregate16(const uint4* __restrict__ h16, float4* __restrict__ agg4,
                              int din8) {
    int n = blockIdx.x * blockDim.y + threadIdx.y;
    if (n >= NN) return;
    int k = threadIdx.x;
    int s = g_row_off[n];
    int e1 = s + g_deg[n];
    float a[8] = {0.f, 0.f, 0.f, 0.f, 0.f, 0.f, 0.f, 0.f};
    int e = s;
    for (; e + 3 < e1; e += 4) {
        int s0 = g_csr_src[e + 0];
        int s1 = g_csr_src[e + 1];
        int s2 = g_csr_src[e + 2];
        int s3 = g_csr_src[e + 3];
        uint4 v0 = h16[(size_t)s0 * din8 + k];
        uint4 v1 = h16[(size_t)s1 * din8 + k];
        uint4 v2 = h16[(size_t)s2 * din8 + k];
        uint4 v3 = h16[(size_t)s3 * din8 + k];
        acc8(a, v0); acc8(a, v1); acc8(a, v2); acc8(a, v3);
    }
    for (; e < e1; e++)
        acc8(a, h16[(size_t)g_csr_src[e] * din8 + k]);
    float di = g_deg_inv[n];
    float4 o0 = make_float4(a[0] * di, a[1] * di, a[2] * di, a[3] * di);
    float4 o1 = make_float4(a[4] * di, a[5] * di, a[6] * di, a[7] * di);
    size_t base = (size_t)n * din8 * 2 + 2 * k;
    agg4[base]     = o0;
    agg4[base + 1] = o1;
}

// ---------------- fp16 (3x hi/lo split) mma.sync SAGE gemm -------------------
__device__ __forceinline__ void split2p(float x, float y, uint32_t& hi2, uint32_t& lo2) {
    asm("cvt.rn.f16x2.f32 %0, %1, %2;" : "=r"(hi2) : "f"(y), "f"(x));
    float hx, hy;
    asm("{\n\t.reg .b16 l, h;\n\tmov.b32 {l, h}, %2;\n\t"
        "cvt.f32.f16 %0, l;\n\tcvt.f32.f16 %1, h;\n\t}"
        : "=f"(hx), "=f"(hy) : "r"(hi2));
    float lx = x - hx, ly = y - hy;
    asm("cvt.rn.f16x2.f32 %0, %1, %2;" : "=r"(lo2) : "f"(ly), "f"(lx));
}

__device__ __forceinline__ void mma_f16(float* c, const uint32_t* a, const uint32_t* b) {
    asm volatile(
        "mma.sync.aligned.m16n8k16.row.col.f32.f16.f16.f32 "
        "{%0,%1,%2,%3}, {%4,%5,%6,%7}, {%8,%9}, {%0,%1,%2,%3};"
        : "+f"(c[0]), "+f"(c[1]), "+f"(c[2]), "+f"(c[3])
        : "r"(a[0]), "r"(a[1]), "r"(a[2]), "r"(a[3]), "r"(b[0]), "r"(b[1]));
}

__device__ __forceinline__ void ldm_x4(uint32_t* r, uint32_t addr) {
    asm volatile("ldmatrix.sync.aligned.m8n8.x4.shared.b16 {%0,%1,%2,%3}, [%4];"
                 : "=r"(r[0]), "=r"(r[1]), "=r"(r[2]), "=r"(r[3]) : "r"(addr));
}
__device__ __forceinline__ void ldm_x2(uint32_t* r, uint32_t addr) {
    asm volatile("ldmatrix.sync.aligned.m8n8.x2.shared.b16 {%0,%1}, [%2];"
                 : "=r"(r[0]), "=r"(r[1]) : "r"(addr));
}

template<int BN>
__global__ __launch_bounds__(256)
void k_gemm_f16(const float* __restrict__ A0, const float* __restrict__ A1,
                const __half* __restrict__ WhiL, const __half* __restrict__ WloL,
                const __half* __restrict__ WhiR, const __half* __restrict__ WloR,
                const float* __restrict__ bias, float* __restrict__ C,
                __half* __restrict__ C16, int din, int dout)
{
    constexpr int WN = BN / 4;
    constexpr int NT = WN / 8;
    constexpr int A_IT = 4;                   // float4 loads / thread
    constexpr int B_IT = BN / 64;             // uint4 (8-half) loads

    __shared__ uint32_t AsH[BM * P32], AsL[BM * P32];
    __shared__ uint32_t BsH[BN * P32], BsL[BN * P32];

    int tid = threadIdx.x;
    int wid = tid >> 5, lane = tid & 31;
    int wm = wid >> 2, wn = wid & 3;
    int lr = lane >> 2, q = lane & 3;
    int rowBase = blockIdx.x * BM;
    int colBase = blockIdx.y * BN;

    int aRow = (lane & 7) + 8 * ((lane >> 3) & 1);
    int aCol = 16 * ((lane >> 4) & 1);
    int bRow = lane & 7;
    int bCol = 16 * ((lane >> 3) & 1);
    uint32_t aBaseH = (uint32_t)__cvta_generic_to_shared(AsH) + (wm * 64 + aRow) * 80 + aCol;
    uint32_t aBaseL = (uint32_t)__cvta_generic_to_shared(AsL) + (wm * 64 + aRow) * 80 + aCol;
    uint32_t bBaseH = (uint32_t)__cvta_generic_to_shared(BsH) + (wn * WN + bRow) * 80 + bCol;
    uint32_t bBaseL = (uint32_t)__cvta_generic_to_shared(BsL) + (wn * WN + bRow) * 80 + bCol;

    float acc[4][NT][4];
    #pragma unroll
    for (int i = 0; i < 4; i++)
        #pragma unroll
        for (int j = 0; j < NT; j++)
            #pragma unroll
            for (int p = 0; p < 4; p++) acc[i][j][p] = 0.0f;

    const int K = 2 * din;
    const int nCh = K >> 5;

    float4 pa[A_IT];
    uint4 pbh[B_IT], pbl[B_IT];

    auto loadChunk = [&](int ch) {
        int k0 = ch << 5;
        const float* Ag;
        const __half *Bh, *Bl;
        int kk;
        if (k0 < din) { Ag = A0; Bh = WhiL; Bl = WloL; kk = k0; }
        else          { Ag = A1; Bh = WhiR; Bl = WloR; kk = k0 - din; }
        #pragma unroll
        for (int it = 0; it < A_IT; it++) {
            int i = tid + it * 256;
            int r = i >> 3, c4 = (i & 7) << 2;
            int gr = rowBase + r;
            pa[it] = (gr < NN) ? *reinterpret_cast<const float4*>(&Ag[(size_t)gr * din + kk + c4])
                               : make_float4(0.f, 0.f, 0.f, 0.f);
        }
        #pragma unroll
        for (int it = 0; it < B_IT; it++) {
            int i = tid + it * 256;
            int r = i >> 2, c8 = (i & 3) << 3;
            size_t goff = (size_t)(colBase + r) * din + kk + c8;
            pbh[it] = *reinterpret_cast<const uint4*>(&Bh[goff]);
            pbl[it] = *reinterpret_cast<const uint4*>(&Bl[goff]);
        }
    };

    loadChunk(0);

    for (int ch = 0; ch < nCh; ch++) {
        // stage A (packed cvt split)
        #pragma unroll
        for (int it = 0; it < A_IT; it++) {
            int i = tid + it * 256;
            int r = i >> 3, w = (i & 7) << 1;
            uint32_t h0, l0, h1, l1;
            split2p(pa[it].x, pa[it].y, h0, l0);
            split2p(pa[it].z, pa[it].w, h1, l1);
            AsH[r * P32 + w] = h0; AsH[r * P32 + w + 1] = h1;
            AsL[r * P32 + w] = l0; AsL[r * P32 + w + 1] = l1;
        }
        // stage B (pure copy of pre-converted weights)
        #pragma unroll
        for (int it = 0; it < B_IT; it++) {
            int i = tid + it * 256;
            int r = i >> 2, w4 = (i & 3) << 2;
            *reinterpret_cast<uint4*>(&BsH[r * P32 + w4]) = pbh[it];
            *reinterpret_cast<uint4*>(&BsL[r * P32 + w4]) = pbl[it];
        }
        __syncthreads();

        if (ch + 1 < nCh) loadChunk(ch + 1);   // GMEM latency overlaps MMA

        #pragma unroll
        for (int ks = 0; ks < 2; ks++) {
            uint32_t kb = (uint32_t)(ks * 32);
            uint32_t ah[4][4], al[4][4], bh[NT][2], bl[NT][2];
            #pragma unroll
            for (int mt = 0; mt < 4; mt++) {
                uint32_t moff = (uint32_t)(mt * 16 * 80) + kb;
                ldm_x4(ah[mt], aBaseH + moff);
                ldm_x4(al[mt], aBaseL + moff);
            }
            #pragma unroll
            for (int nt = 0; nt < NT; nt++) {
                uint32_t noff = (uint32_t)(nt * 8 * 80) + kb;
                ldm_x2(bh[nt], bBaseH + noff);
                ldm_x2(bl[nt], bBaseL + noff);
            }
            #pragma unroll
            for (int mt = 0; mt < 4; mt++)
                #pragma unroll
                for (int nt = 0; nt < NT; nt++)
                    mma_f16(acc[mt][nt], ah[mt], bh[nt]);
            #pragma unroll
            for (int mt = 0; mt < 4; mt++)
                #pragma unroll
                for (int nt = 0; nt < NT; nt++)
                    mma_f16(acc[mt][nt], al[mt], bh[nt]);
            #pragma unroll
            for (int mt = 0; mt < 4; mt++)
                #pragma unroll
                for (int nt = 0; nt < NT; nt++)
                    mma_f16(acc[mt][nt], ah[mt], bl[nt]);
        }
        __syncthreads();
    }

    // epilogue: bias + relu + fp32 store + fp16 copy for next-layer gathers
    #pragma unroll
    for (int mt = 0; mt < 4; mt++) {
        int r0 = rowBase + wm * 64 + mt * 16 + lr;
        int r1 = r0 + 8;
        #pragma unroll
        for (int nt = 0; nt < NT; nt++) {
            int c = colBase + wn * WN + nt * 8 + q * 2;
            float b0 = bias[c], b1 = bias[c + 1];
            if (r0 < NN) {
                float v0 = fmaxf(acc[mt][nt][0] + b0, 0.f);
                float v1 = fmaxf(acc[mt][nt][1] + b1, 0.f);
                float2 v; v.x = v0; v.y = v1;
                *reinterpret_cast<float2*>(&C[(size_t)r0 * dout + c]) = v;
                uint32_t p;
                asm("cvt.rn.f16x2.f32 %0, %1, %2;" : "=r"(p) : "f"(v1), "f"(v0));
                *reinterpret_cast<uint32_t*>(&C16[(size_t)r0 * dout + c]) = p;
            }
            if (r1 < NN) {
                float v0 = fmaxf(acc[mt][nt][2] + b0, 0.f);
                float v1 = fmaxf(acc[mt][nt][3] + b1, 0.f);
                float2 v; v.x = v0; v.y = v1;
                *reinterpret_cast<float2*>(&C[(size_t)r1 * dout + c]) = v;
                uint32_t p;
                asm("cvt.rn.f16x2.f32 %0, %1, %2;" : "=r"(p) : "f"(v1), "f"(v0));
                *reinterpret_cast<uint32_t*>(&C16[(size_t)r1 * dout + c]) = p;
            }
        }
    }
}

// ---------------- head: logits = h @ Wout^T + bout; softmax -----------------
__global__ void k_head(const float4* __restrict__ h4, const float4* __restrict__ Wout4,
                       const float* __restrict__ bout, float* __restrict__ out) {
    int gwarp = (blockIdx.x * blockDim.x + threadIdx.x) >> 5;
    int lane  = threadIdx.x & 31;
    if (gwarp >= NN) return;
    const float4* hr = h4 + (size_t)gwarp * 128;
    float s[4] = {0.f, 0.f, 0.f, 0.f};
    #pragma unroll
    for (int it = 0; it < 4; it++) {
        int i = lane + it * 32;
        float4 hv = hr[i];
        #pragma unroll
        for (int c = 0; c < 4; c++) {
            float4 wv = Wout4[c * 128 + i];
            s[c] += hv.x * wv.x + hv.y * wv.y + hv.z * wv.z + hv.w * wv.w;
        }
    }
    #pragma unroll
    for (int off = 16; off > 0; off >>= 1)
        #pragma unroll
        for (int c = 0; c < 4; c++)
            s[c] += __shfl_xor_sync(0xFFFFFFFF, s[c], off);
    if (lane == 0) {
        float l[4];
        float m = -1e30f;
        #pragma unroll
        for (int c = 0; c < 4; c++) { l[c] = s[c] + bout[c]; m = fmaxf(m, l[c]); }
        float den = 0.f;
        #pragma unroll
        for (int c = 0; c < 4; c++) { l[c] = __expf(l[c] - m); den += l[c]; }
        float inv = 1.0f / den;
        #pragma unroll
        for (int c = 0; c < 4; c++) out[(size_t)gwarp * 4 + c] = l[c] * inv;
    }
}

// ---------------- driver -----------------------------------------------------
extern "C" void kernel_launch(void* const* d_in, const int* in_sizes, int n_in,
                              void* d_out, int out_size)
{
    const float* x    = (const float*)d_in[0];
    const float* Wl[5] = {(const float*)d_in[1],  (const float*)d_in[4],
                          (const float*)d_in[7],  (const float*)d_in[10],
                          (const float*)d_in[13]};
    const float* bl[5] = {(const float*)d_in[2],  (const float*)d_in[5],
                          (const float*)d_in[8],  (const float*)d_in[11],
                          (const float*)d_in[14]};
    const float* Wr[5] = {(const float*)d_in[3],  (const float*)d_in[6],
                          (const float*)d_in[9],  (const float*)d_in[12],
                          (const float*)d_in[15]};
    const float* Wout = (const float*)d_in[16];
    const float* bout = (const float*)d_in[17];
    const int*   ei   = (const int*)d_in[18];
    const int* src = ei;
    const int* dst = ei + EE;

    float *bufA, *bufB, *aggp;
    __half *whi, *wlo, *x16, *h16A, *h16B;
    cudaGetSymbolAddress((void**)&bufA, g_bufA);
    cudaGetSymbolAddress((void**)&bufB, g_bufB);
    cudaGetSymbolAddress((void**)&aggp, g_agg);
    cudaGetSymbolAddress((void**)&whi, g_Whi);
    cudaGetSymbolAddress((void**)&wlo, g_Wlo);
    cudaGetSymbolAddress((void**)&x16, g_x16);
    cudaGetSymbolAddress((void**)&h16A, g_h16A);
    cudaGetSymbolAddress((void**)&h16B, g_h16B);

    // 0. convert weights + input once per call
    WP wp;
    for (int i = 0; i < 5; i++) { wp.w[2 * i] = Wl[i]; wp.w[2 * i + 1] = Wr[i]; }
    k_convW<<<(NWTOT + 255) / 256, 256>>>(wp);
    k_convX16<<<(NN * 64 + 255) / 256, 256>>>((const float2*)x);

    // 1. build CSR by dst
    k_zero_deg<<<(NN + 255) / 256, 256>>>();
    k_count_deg<<<(EE + 255) / 256, 256>>>(dst);
    k_offsets<<<(NN + 255) / 256, 256>>>();
    k_fill_csr<<<(EE + 255) / 256, 256>>>(src, dst);

    // 2. layers
    const int dins[5]  = {128, 128, 64, 128, 256};
    const int douts[5] = {128,  64, 128, 256, 512};
    const int woff[10] = {0, 16384, 32768, 40960, 49152, 57344,
                          65536, 98304, 131072, 262144};
    const float* hcur = x;
    const __half* h16cur = x16;
    float* bufs[2] = {bufA, bufB};
    __half* bufs16[2] = {h16A, h16B};
    for (int i = 0; i < 5; i++) {
        int din = dins[i], dout = douts[i];
        int din8 = din / 8;
        int npb = 128 / din8;
        dim3 ablk(din8, npb);
        k_aggregate16<<<(NN + npb - 1) / npb, ablk>>>(
            (const uint4*)h16cur, (float4*)aggp, din8);
        float* hnext = bufs[i & 1];
        __half* h16next = bufs16[i & 1];
        const __half* whl = whi + woff[2 * i];
        const __half* wll = wlo + woff[2 * i];
        const __half* whr = whi + woff[2 * i + 1];
        const __half* wlr = wlo + woff[2 * i + 1];
        if (dout >= 128) {
            dim3 grid((NN + BM - 1) / BM, dout / 128);
            k_gemm_f16<128><<<grid, 256>>>(aggp, hcur, whl, wll, whr, wlr,
                                           bl[i], hnext, h16next, din, dout);
        } else {
            dim3 grid((NN + BM - 1) / BM, 1);
            k_gemm_f16<64><<<grid, 256>>>(aggp, hcur, whl, wll, whr, wlr,
                                          bl[i], hnext, h16next, din, dout);
        }
        hcur = hnext;
        h16cur = h16next;
    }

    // 3. head + softmax
    k_head<<<(NN * 32 + 255) / 256, 256>>>((const float4*)hcur, (const float4*)Wout,
                                           bout, (float*)d_out);
}